// round 13
// baseline (speedup 1.0000x reference)
#include <cuda_runtime.h>
#include <cuda_bf16.h>
#include <cstdint>

// GAT B=32768, N=16, FIN=64, H=4, FO=32. nf = X@W via mma.sync m16n8k16
// bf16 3-split. R13: XOR-swizzled 128B tile rows (no pad), NF staging
// overlays A/SB region, ASH packed float4 -> 71KB/CTA -> 3 CTAs/SM.
typedef unsigned long long ull;
struct alignas(16) ull2x { ull a, b; };

#define WTHI 0
#define WTLO 16384
#define WFHI 32768
#define WFLO 33792
#define PWB  34816
#define A_HI 0
#define A_LO 2048
#define SB_  4096
#define NF_  0
#define ASH_ 8448
#define PWSZ 9472
#define SMEM_SZ (PWB + 4 * PWSZ)     // 72704 B -> 3 CTAs/SM

static __device__ __forceinline__ uint32_t s2u(const void* p) {
    uint32_t a;
    asm("{ .reg .u64 t; cvta.to.shared.u64 t, %1; cvt.u32.u64 %0, t; }" : "=r"(a) : "l"(p));
    return a;
}
static __device__ __forceinline__ uint32_t swz(uint32_t row, uint32_t chunk) {
    return row * 128 + ((chunk ^ (row & 7)) * 16);
}
static __device__ __forceinline__ void ffma2(ull& d, ull a, ull b) {
    asm("fma.rn.f32x2 %0, %1, %2, %0;" : "+l"(d) : "l"(a), "l"(b));
}
static __device__ __forceinline__ ull pack2(float lo, float hi) {
    ull r; asm("mov.b64 %0, {%1, %2};" : "=l"(r) : "f"(lo), "f"(hi)); return r;
}
static __device__ __forceinline__ uint32_t cvt2(float lo, float hi) {
    uint32_t r; asm("cvt.rn.satfinite.bf16x2.f32 %0, %1, %2;" : "=r"(r) : "f"(hi), "f"(lo));
    return r;
}
static __device__ __forceinline__ void ldmx4(uint32_t& r0, uint32_t& r1, uint32_t& r2,
                                             uint32_t& r3, uint32_t addr) {
    asm volatile("ldmatrix.sync.aligned.m8n8.x4.shared.b16 {%0,%1,%2,%3}, [%4];"
                 : "=r"(r0), "=r"(r1), "=r"(r2), "=r"(r3) : "r"(addr));
}
static __device__ __forceinline__ void mma4(float* d, const uint32_t* a,
                                            uint32_t b0, uint32_t b1) {
    asm volatile("mma.sync.aligned.m16n8k16.row.col.f32.bf16.bf16.f32 "
                 "{%0,%1,%2,%3},{%4,%5,%6,%7},{%8,%9},{%0,%1,%2,%3};"
                 : "+f"(d[0]), "+f"(d[1]), "+f"(d[2]), "+f"(d[3])
                 : "r"(a[0]), "r"(a[1]), "r"(a[2]), "r"(a[3]), "r"(b0), "r"(b1));
}

__device__ float g_av[256];
__global__ void select_av_kernel(const float* __restrict__ ca, const float* __restrict__ cb) {
    __shared__ int nb; int t = threadIdx.x;
    if (t == 0) nb = 0;
    __syncthreads();
    float v = ca[t];
    if (!(v == 0.0f || v == 1.0f)) atomicAdd(&nb, 1);
    __syncthreads();
    g_av[t] = (nb > 0) ? ca[t] : cb[t];
}

__global__ void __launch_bounds__(128)
gat_kernel(const float* __restrict__ x, const float* __restrict__ W,
           float* __restrict__ out, int n_batch)
{
    extern __shared__ char sm[];
    const uint32_t sb = s2u(sm);
    const int tid = threadIdx.x, lane = tid & 31, wid = tid >> 5;

    // ---- init: Wt hi/lo (swizzled 128B rows) + wfoldT hi/lo ----
    for (int idx = tid; idx < 8192; idx += 128) {
        int cg = idx >> 6, f = idx & 63;
        float w = W[f * 128 + cg];
        __nv_bfloat16 h = __float2bfloat16_rn(w);
        uint32_t a = swz(cg, f >> 3) + (f & 7) * 2;
        *reinterpret_cast<__nv_bfloat16*>(sm + WTHI + a) = h;
        *reinterpret_cast<__nv_bfloat16*>(sm + WTLO + a) =
            __float2bfloat16_rn(w - __bfloat162float(h));
    }
    for (int e = tid; e < 512; e += 128) {
        int f = e >> 3, n = e & 7, side = n >> 2, h = n & 3;
        const float* wr = W + f * 128;
        const float* ar = g_av + h * 64 + side * 32;
        float s = 0.f;
        #pragma unroll 8
        for (int k = 0; k < 32; k++)
            s += (wr[k] + wr[32 + k] + wr[64 + k] + wr[96 + k]) * ar[k];
        __nv_bfloat16 hb = __float2bfloat16_rn(s);
        uint32_t a = swz(n, f >> 3) + (f & 7) * 2;
        *reinterpret_cast<__nv_bfloat16*>(sm + WFHI + a) = hb;
        *reinterpret_cast<__nv_bfloat16*>(sm + WFLO + a) =
            __float2bfloat16_rn(s - __bfloat162float(hb));
    }
    __syncthreads();

    char* pw = sm + PWB + wid * PWSZ;
    const uint32_t aw = sb + PWB + wid * PWSZ;
    const int myh = lane >> 3;

    for (int b = blockIdx.x * 4 + wid; b < n_batch; b += gridDim.x * 4) {
        // ---- X -> bf16 hi/lo A tiles (swizzled 128B rows) ----
        const float4* xg = reinterpret_cast<const float4*>(x + (size_t)b * 1024);
        #pragma unroll
        for (int t = 0; t < 8; t++) {
            int fid = t * 32 + lane;
            float4 v = xg[fid];
            uint32_t h01 = cvt2(v.x, v.y), h23 = cvt2(v.z, v.w);
            float l0 = v.x - __uint_as_float(h01 << 16);
            float l1 = v.y - __uint_as_float(h01 & 0xFFFF0000u);
            float l2 = v.z - __uint_as_float(h23 << 16);
            float l3 = v.w - __uint_as_float(h23 & 0xFFFF0000u);
            int row = fid >> 4, q = fid & 15;
            uint32_t off = swz(row, q >> 1) + (q & 1) * 8;
            *reinterpret_cast<uint2*>(pw + A_HI + off) = make_uint2(h01, h23);
            *reinterpret_cast<uint2*>(pw + A_LO + off) = make_uint2(cvt2(l0, l1), cvt2(l2, l3));
        }
        __syncwarp();

        // ---- A fragments (4 k-steps, hi/lo) ----
        uint32_t ah[16], al[16];
        #pragma unroll
        for (int kt = 0; kt < 4; kt++) {
            uint32_t c = 2 * kt + (lane >> 4);
            uint32_t o = swz(lane & 15, c);
            ldmx4(ah[4 * kt], ah[4 * kt + 1], ah[4 * kt + 2], ah[4 * kt + 3], aw + A_HI + o);
            ldmx4(al[4 * kt], al[4 * kt + 1], al[4 * kt + 2], al[4 * kt + 3], aw + A_LO + o);
        }

        // ---- scores via mma: s(16x8) = X @ wfoldT^T ----
        {
            uint32_t fr = lane & 7, fc = lane >> 3;
            uint32_t fh[8], fl[8];
            ldmx4(fh[0], fh[1], fh[2], fh[3], sb + WFHI + swz(fr, fc));
            ldmx4(fh[4], fh[5], fh[6], fh[7], sb + WFHI + swz(fr, fc + 4));
            ldmx4(fl[0], fl[1], fl[2], fl[3], sb + WFLO + swz(fr, fc));
            ldmx4(fl[4], fl[5], fl[6], fl[7], sb + WFLO + swz(fr, fc + 4));
            float s[4] = {0.f, 0.f, 0.f, 0.f};
            #pragma unroll
            for (int kt = 0; kt < 4; kt++) {
                int bi = (kt >> 1) * 4 + (kt & 1) * 2;
                mma4(s, &ah[4 * kt], fh[bi], fh[bi + 1]);
            }
            #pragma unroll
            for (int kt = 0; kt < 4; kt++) {
                int bi = (kt >> 1) * 4 + (kt & 1) * 2;
                mma4(s, &al[4 * kt], fh[bi], fh[bi + 1]);
            }
            #pragma unroll
            for (int kt = 0; kt < 4; kt++) {
                int bi = (kt >> 1) * 4 + (kt & 1) * 2;
                mma4(s, &ah[4 * kt], fl[bi], fl[bi + 1]);
            }
            int c = 2 * (lane & 3), r = lane >> 2, side = c >> 2, cc = c & 3;
            *reinterpret_cast<float2*>(pw + SB_ + (side * 16 + r) * 16 + cc * 4) =
                make_float2(s[0], s[1]);
            *reinterpret_cast<float2*>(pw + SB_ + (side * 16 + r + 8) * 16 + cc * 4) =
                make_float2(s[2], s[3]);
        }
        __syncwarp();

        // ---- softmax over {i-1,i,i+1,i^8}; ash[i][h] = float4 over slots ----
        {
            int i = lane & 15, hp = lane >> 4;
            float2 s1v = *reinterpret_cast<const float2*>(pw + SB_ + i * 16 + hp * 8);
            int jn[4] = { (i > 0) ? i - 1 : i, i, (i < 15) ? i + 1 : i, i ^ 8 };
            bool vl[4] = { i > 0, true, i < 15, true };
            float t0[4], t1[4];
            float m0 = -1e30f, m1 = -1e30f;
            #pragma unroll
            for (int s = 0; s < 4; s++) {
                float2 s2v = *reinterpret_cast<const float2*>(pw + SB_ + 256 + jn[s] * 16 + hp * 8);
                float a0 = s1v.x + s2v.x; a0 = fmaxf(a0, 0.2f * a0);
                float a1 = s1v.y + s2v.y; a1 = fmaxf(a1, 0.2f * a1);
                t0[s] = vl[s] ? a0 : -1e30f;
                t1[s] = vl[s] ? a1 : -1e30f;
                m0 = fmaxf(m0, t0[s]); m1 = fmaxf(m1, t1[s]);
            }
            float sum0 = 0.f, sum1 = 0.f;
            #pragma unroll
            for (int s = 0; s < 4; s++) {
                t0[s] = __expf(t0[s] - m0);
                t1[s] = __expf(t1[s] - m1);
                sum0 += t0[s]; sum1 += t1[s];
            }
            float r0 = __fdividef(1.f, sum0), r1 = __fdividef(1.f, sum1);
            *reinterpret_cast<float4*>(pw + ASH_ + (i * 4 + 2 * hp) * 16) =
                make_float4(t0[0] * r0, t0[1] * r0, t0[2] * r0, t0[3] * r0);
            *reinterpret_cast<float4*>(pw + ASH_ + (i * 4 + 2 * hp + 1) * 16) =
                make_float4(t1[0] * r1, t1[1] * r1, t1[2] * r1, t1[3] * r1);
        }
        __syncwarp();   // SB fully consumed before NF overlays it

        // ---- main GEMM: nf = X@W, 16 n-tiles, 3-split; NF overlays A/SB ----
        for (int nt = 0; nt < 16; nt += 2) {
            uint32_t cg0 = nt * 8 + (lane & 7), cg1 = cg0 + 8, kc = lane >> 3;
            uint32_t bh0[8], bl0[8], bh1[8], bl1[8];
            ldmx4(bh0[0], bh0[1], bh0[2], bh0[3], sb + WTHI + swz(cg0, kc));
            ldmx4(bh0[4], bh0[5], bh0[6], bh0[7], sb + WTHI + swz(cg0, kc + 4));
            ldmx4(bh1[0], bh1[1], bh1[2], bh1[3], sb + WTHI + swz(cg1, kc));
            ldmx4(bh1[4], bh1[5], bh1[6], bh1[7], sb + WTHI + swz(cg1, kc + 4));
            ldmx4(bl0[0], bl0[1], bl0[2], bl0[3], sb + WTLO + swz(cg0, kc));
            ldmx4(bl0[4], bl0[5], bl0[6], bl0[7], sb + WTLO + swz(cg0, kc + 4));
            ldmx4(bl1[0], bl1[1], bl1[2], bl1[3], sb + WTLO + swz(cg1, kc));
            ldmx4(bl1[4], bl1[5], bl1[6], bl1[7], sb + WTLO + swz(cg1, kc + 4));

            float d0[4] = {0.f, 0.f, 0.f, 0.f}, d1[4] = {0.f, 0.f, 0.f, 0.f};
            #pragma unroll
            for (int kt = 0; kt < 4; kt++) {
                int bi = (kt >> 1) * 4 + (kt & 1) * 2;
                mma4(d0, &ah[4 * kt], bh0[bi], bh0[bi + 1]);
                mma4(d1, &ah[4 * kt], bh1[bi], bh1[bi + 1]);
            }
            #pragma unroll
            for (int kt = 0; kt < 4; kt++) {
                int bi = (kt >> 1) * 4 + (kt & 1) * 2;
                mma4(d0, &al[4 * kt], bh0[bi], bh0[bi + 1]);
                mma4(d1, &al[4 * kt], bh1[bi], bh1[bi + 1]);
            }
            #pragma unroll
            for (int kt = 0; kt < 4; kt++) {
                int bi = (kt >> 1) * 4 + (kt & 1) * 2;
                mma4(d0, &ah[4 * kt], bl0[bi], bl0[bi + 1]);
                mma4(d1, &ah[4 * kt], bl1[bi], bl1[bi + 1]);
            }
            int c = 2 * (lane & 3), r = lane >> 2;
            *reinterpret_cast<float2*>(pw + NF_ + r * 528 + (nt * 8 + c) * 4) =
                make_float2(d0[0], d0[1]);
            *reinterpret_cast<float2*>(pw + NF_ + (r + 8) * 528 + (nt * 8 + c) * 4) =
                make_float2(d0[2], d0[3]);
            *reinterpret_cast<float2*>(pw + NF_ + r * 528 + ((nt + 1) * 8 + c) * 4) =
                make_float2(d1[0], d1[1]);
            *reinterpret_cast<float2*>(pw + NF_ + (r + 8) * 528 + ((nt + 1) * 8 + c) * 4) =
                make_float2(d1[2], d1[3]);
        }
        __syncwarp();

        // ---- agg over {i-1,i,i+1,i^8} + STG.128 ----
        float* ob = out + (size_t)b * 2048;
        #pragma unroll
        for (int i = 0; i < 16; i++) {
            int jn0 = (i > 0) ? i - 1 : i, jn2 = (i < 15) ? i + 1 : i;
            float4 av = *reinterpret_cast<const float4*>(pw + ASH_ + (i * 4 + myh) * 16);
            ull a0 = pack2(av.x, av.x), a1 = pack2(av.y, av.y);
            ull a2 = pack2(av.z, av.z), a3 = pack2(av.w, av.w);
            ull2x q0 = *reinterpret_cast<const ull2x*>(pw + NF_ + jn0 * 528 + lane * 16);
            ull2x q1 = *reinterpret_cast<const ull2x*>(pw + NF_ + i   * 528 + lane * 16);
            ull2x q2 = *reinterpret_cast<const ull2x*>(pw + NF_ + jn2 * 528 + lane * 16);
            ull2x q3 = *reinterpret_cast<const ull2x*>(pw + NF_ + (i ^ 8) * 528 + lane * 16);
            ull o0 = 0ull, o1 = 0ull;
            ffma2(o0, a0, q0.a); ffma2(o1, a0, q0.b);
            ffma2(o0, a1, q1.a); ffma2(o1, a1, q1.b);
            ffma2(o0, a2, q2.a); ffma2(o1, a2, q2.b);
            ffma2(o0, a3, q3.a); ffma2(o1, a3, q3.b);
            ull2x vv; vv.a = o0; vv.b = o1;
            *reinterpret_cast<ull2x*>(&ob[i * 128 + 4 * lane]) = vv;
        }
        __syncwarp();
    }
}

extern "C" void kernel_launch(void* const* d_in, const int* in_sizes, int n_in,
                              void* d_out, int out_size)
{
    const float* x  = (const float*)d_in[0];
    const float* W  = (const float*)d_in[1];
    const float* c2 = (const float*)d_in[2];
    const float* c3 = (const float*)d_in[3];
    float* out = (float*)d_out;
    int n_batch = in_sizes[0] / 1024;   // 32768

    select_av_kernel<<<1, 256>>>(c2, c3);
    cudaFuncSetAttribute(gat_kernel, cudaFuncAttributeMaxDynamicSharedMemorySize, SMEM_SZ);
    gat_kernel<<<444, 128, SMEM_SZ>>>(x, W, out, n_batch);
}

// round 14
// speedup vs baseline: 1.2848x; 1.2848x over previous
#include <cuda_runtime.h>
#include <cuda_bf16.h>
#include <cstdint>

// GAT B=32768, N=16, FIN=64, H=4, FO=32. nf = X@W on tensor cores via
// mma.sync.m16n8k16 bf16 3-split. R14: R12 layout (144B pitch, proven),
// split accumulators (dep depth 12 -> 4) + full unroll for ILP.
typedef unsigned long long ull;
struct alignas(16) ull2x { ull a, b; };

#define WTHI 0
#define WTLO 18432
#define WFHI 36864
#define WFLO 38016
#define PWB  39168
#define A_HI 0
#define A_LO 2304
#define NF_  4608
#define SB_  13056
#define ASH_ 13568
#define PWSZ 15616
#define SMEM_SZ (PWB + 4 * PWSZ)     // 101632 B -> 2 CTAs/SM

static __device__ __forceinline__ uint32_t s2u(const void* p) {
    uint32_t a;
    asm("{ .reg .u64 t; cvta.to.shared.u64 t, %1; cvt.u32.u64 %0, t; }" : "=r"(a) : "l"(p));
    return a;
}
static __device__ __forceinline__ void ffma2(ull& d, ull a, ull b) {
    asm("fma.rn.f32x2 %0, %1, %2, %0;" : "+l"(d) : "l"(a), "l"(b));
}
static __device__ __forceinline__ uint32_t cvt2(float lo, float hi) {
    uint32_t r; asm("cvt.rn.satfinite.bf16x2.f32 %0, %1, %2;" : "=r"(r) : "f"(hi), "f"(lo));
    return r;
}
static __device__ __forceinline__ void ldmx4(uint32_t& r0, uint32_t& r1, uint32_t& r2,
                                             uint32_t& r3, uint32_t addr) {
    asm volatile("ldmatrix.sync.aligned.m8n8.x4.shared.b16 {%0,%1,%2,%3}, [%4];"
                 : "=r"(r0), "=r"(r1), "=r"(r2), "=r"(r3) : "r"(addr));
}
static __device__ __forceinline__ void mma4(float* d, const uint32_t* a,
                                            uint32_t b0, uint32_t b1) {
    asm volatile("mma.sync.aligned.m16n8k16.row.col.f32.bf16.bf16.f32 "
                 "{%0,%1,%2,%3},{%4,%5,%6,%7},{%8,%9},{%0,%1,%2,%3};"
                 : "+f"(d[0]), "+f"(d[1]), "+f"(d[2]), "+f"(d[3])
                 : "r"(a[0]), "r"(a[1]), "r"(a[2]), "r"(a[3]), "r"(b0), "r"(b1));
}

__device__ float g_av[256];
__global__ void select_av_kernel(const float* __restrict__ ca, const float* __restrict__ cb) {
    __shared__ int nb; int t = threadIdx.x;
    if (t == 0) nb = 0;
    __syncthreads();
    float v = ca[t];
    if (!(v == 0.0f || v == 1.0f)) atomicAdd(&nb, 1);
    __syncthreads();
    g_av[t] = (nb > 0) ? ca[t] : cb[t];
}

__global__ void __launch_bounds__(128)
gat_kernel(const float* __restrict__ x, const float* __restrict__ W,
           float* __restrict__ out, int n_batch)
{
    extern __shared__ char sm[];
    const uint32_t sb = s2u(sm);
    const int tid = threadIdx.x, lane = tid & 31, wid = tid >> 5;

    // ---- init: Wt hi/lo (K-major rows, 144B pitch) + wfoldT hi/lo ----
    for (int idx = tid; idx < 8192; idx += 128) {
        int cg = idx >> 6, f = idx & 63;
        float w = W[f * 128 + cg];
        __nv_bfloat16 h = __float2bfloat16_rn(w);
        *reinterpret_cast<__nv_bfloat16*>(sm + WTHI + cg * 144 + f * 2) = h;
        *reinterpret_cast<__nv_bfloat16*>(sm + WTLO + cg * 144 + f * 2) =
            __float2bfloat16_rn(w - __bfloat162float(h));
    }
    for (int e = tid; e < 512; e += 128) {
        int f = e >> 3, n = e & 7, side = n >> 2, h = n & 3;
        const float* wr = W + f * 128;
        const float* ar = g_av + h * 64 + side * 32;
        float s = 0.f;
        #pragma unroll 8
        for (int k = 0; k < 32; k++)
            s += (wr[k] + wr[32 + k] + wr[64 + k] + wr[96 + k]) * ar[k];
        __nv_bfloat16 hb = __float2bfloat16_rn(s);
        *reinterpret_cast<__nv_bfloat16*>(sm + WFHI + n * 144 + f * 2) = hb;
        *reinterpret_cast<__nv_bfloat16*>(sm + WFLO + n * 144 + f * 2) =
            __float2bfloat16_rn(s - __bfloat162float(hb));
    }
    __syncthreads();

    char* pw = sm + PWB + wid * PWSZ;
    const uint32_t aw = sb + PWB + wid * PWSZ;
    const int myh = lane >> 3;

    for (int b = blockIdx.x * 4 + wid; b < n_batch; b += gridDim.x * 4) {
        // ---- X -> bf16 hi/lo A tiles (row pitch 144B) ----
        const float4* xg = reinterpret_cast<const float4*>(x + (size_t)b * 1024);
        #pragma unroll
        for (int t = 0; t < 8; t++) {
            int fid = t * 32 + lane;
            float4 v = xg[fid];
            uint32_t h01 = cvt2(v.x, v.y), h23 = cvt2(v.z, v.w);
            float l0 = v.x - __uint_as_float(h01 << 16);
            float l1 = v.y - __uint_as_float(h01 & 0xFFFF0000u);
            float l2 = v.z - __uint_as_float(h23 << 16);
            float l3 = v.w - __uint_as_float(h23 & 0xFFFF0000u);
            int off = (fid >> 4) * 144 + (fid & 15) * 8;
            *reinterpret_cast<uint2*>(pw + A_HI + off) = make_uint2(h01, h23);
            *reinterpret_cast<uint2*>(pw + A_LO + off) = make_uint2(cvt2(l0, l1), cvt2(l2, l3));
        }
        __syncwarp();

        // ---- A fragments (4 k-steps, hi and lo) ----
        uint32_t ah[16], al[16];
        {
            uint32_t ab = aw + A_HI + (lane & 15) * 144 + (lane >> 4) * 16;
            #pragma unroll
            for (int kt = 0; kt < 4; kt++)
                ldmx4(ah[4 * kt], ah[4 * kt + 1], ah[4 * kt + 2], ah[4 * kt + 3], ab + kt * 32);
            uint32_t lb = ab + (A_LO - A_HI);
            #pragma unroll
            for (int kt = 0; kt < 4; kt++)
                ldmx4(al[4 * kt], al[4 * kt + 1], al[4 * kt + 2], al[4 * kt + 3], lb + kt * 32);
        }

        // ---- scores via mma (3 independent chains, depth 4) ----
        {
            uint32_t fb = sb + WFHI + (lane & 7) * 144 + (lane >> 3) * 16;
            uint32_t fh[8], fl[8];
            ldmx4(fh[0], fh[1], fh[2], fh[3], fb);
            ldmx4(fh[4], fh[5], fh[6], fh[7], fb + 64);
            ldmx4(fl[0], fl[1], fl[2], fl[3], fb + (WFLO - WFHI));
            ldmx4(fl[4], fl[5], fl[6], fl[7], fb + (WFLO - WFHI) + 64);
            float sA[4] = {0, 0, 0, 0}, sB[4] = {0, 0, 0, 0}, sC[4] = {0, 0, 0, 0};
            #pragma unroll
            for (int kt = 0; kt < 4; kt++) {
                int bi = (kt >> 1) * 4 + (kt & 1) * 2;
                mma4(sA, &ah[4 * kt], fh[bi], fh[bi + 1]);
                mma4(sB, &al[4 * kt], fh[bi], fh[bi + 1]);
                mma4(sC, &ah[4 * kt], fl[bi], fl[bi + 1]);
            }
            float s[4];
            #pragma unroll
            for (int q = 0; q < 4; q++) s[q] = sA[q] + sB[q] + sC[q];
            int c = 2 * (lane & 3), r = lane >> 2, side = c >> 2, cc = c & 3;
            *reinterpret_cast<float2*>(pw + SB_ + (side * 16 + r) * 16 + cc * 4) =
                make_float2(s[0], s[1]);
            *reinterpret_cast<float2*>(pw + SB_ + (side * 16 + r + 8) * 16 + cc * 4) =
                make_float2(s[2], s[3]);
        }
        __syncwarp();

        // ---- softmax over {i-1,i,i+1,i^8}; ash[i][h][slot] = {a,a} ----
        {
            int i = lane & 15, hp = lane >> 4;
            float2 s1v = *reinterpret_cast<const float2*>(pw + SB_ + i * 16 + hp * 8);
            int jn[4] = { (i > 0) ? i - 1 : i, i, (i < 15) ? i + 1 : i, i ^ 8 };
            bool vl[4] = { i > 0, true, i < 15, true };
            float t0[4], t1[4];
            float m0 = -1e30f, m1 = -1e30f;
            #pragma unroll
            for (int s = 0; s < 4; s++) {
                float2 s2v = *reinterpret_cast<const float2*>(pw + SB_ + 256 + jn[s] * 16 + hp * 8);
                float a0 = s1v.x + s2v.x; a0 = fmaxf(a0, 0.2f * a0);
                float a1 = s1v.y + s2v.y; a1 = fmaxf(a1, 0.2f * a1);
                t0[s] = vl[s] ? a0 : -1e30f;
                t1[s] = vl[s] ? a1 : -1e30f;
                m0 = fmaxf(m0, t0[s]); m1 = fmaxf(m1, t1[s]);
            }
            float sum0 = 0.f, sum1 = 0.f;
            #pragma unroll
            for (int s = 0; s < 4; s++) {
                t0[s] = __expf(t0[s] - m0);
                t1[s] = __expf(t1[s] - m1);
                sum0 += t0[s]; sum1 += t1[s];
            }
            float r0 = __fdividef(1.f, sum0), r1 = __fdividef(1.f, sum1);
            #pragma unroll
            for (int s = 0; s < 4; s++) {
                float v0 = t0[s] * r0, v1 = t1[s] * r1;
                *reinterpret_cast<float2*>(pw + ASH_ + ((i * 4 + 2 * hp) * 4 + s) * 8) =
                    make_float2(v0, v0);
                *reinterpret_cast<float2*>(pw + ASH_ + ((i * 4 + 2 * hp + 1) * 4 + s) * 8) =
                    make_float2(v1, v1);
            }
        }

        // ---- main GEMM: 8 tile-pairs, 3 chains per tile (depth 4), unrolled ----
        #pragma unroll
        for (int nt = 0; nt < 16; nt += 2) {
            uint32_t wb0 = sb + WTHI + (nt * 8 + (lane & 7)) * 144 + (lane >> 3) * 16;
            uint32_t wb1 = wb0 + 8 * 144;
            uint32_t bh0[8], bl0[8], bh1[8], bl1[8];
            ldmx4(bh0[0], bh0[1], bh0[2], bh0[3], wb0);
            ldmx4(bh0[4], bh0[5], bh0[6], bh0[7], wb0 + 64);
            ldmx4(bh1[0], bh1[1], bh1[2], bh1[3], wb1);
            ldmx4(bh1[4], bh1[5], bh1[6], bh1[7], wb1 + 64);
            ldmx4(bl0[0], bl0[1], bl0[2], bl0[3], wb0 + (WTLO - WTHI));
            ldmx4(bl0[4], bl0[5], bl0[6], bl0[7], wb0 + (WTLO - WTHI) + 64);
            ldmx4(bl1[0], bl1[1], bl1[2], bl1[3], wb1 + (WTLO - WTHI));
            ldmx4(bl1[4], bl1[5], bl1[6], bl1[7], wb1 + (WTLO - WTHI) + 64);

            float d0A[4] = {0, 0, 0, 0}, d0B[4] = {0, 0, 0, 0}, d0C[4] = {0, 0, 0, 0};
            float d1A[4] = {0, 0, 0, 0}, d1B[4] = {0, 0, 0, 0}, d1C[4] = {0, 0, 0, 0};
            #pragma unroll
            for (int kt = 0; kt < 4; kt++) {
                int bi = (kt >> 1) * 4 + (kt & 1) * 2;
                mma4(d0A, &ah[4 * kt], bh0[bi], bh0[bi + 1]);
                mma4(d1A, &ah[4 * kt], bh1[bi], bh1[bi + 1]);
                mma4(d0B, &al[4 * kt], bh0[bi], bh0[bi + 1]);
                mma4(d1B, &al[4 * kt], bh1[bi], bh1[bi + 1]);
                mma4(d0C, &ah[4 * kt], bl0[bi], bl0[bi + 1]);
                mma4(d1C, &ah[4 * kt], bl1[bi], bl1[bi + 1]);
            }
            float d0[4], d1[4];
            #pragma unroll
            for (int q = 0; q < 4; q++) {
                d0[q] = d0A[q] + d0B[q] + d0C[q];
                d1[q] = d1A[q] + d1B[q] + d1C[q];
            }
            int c = 2 * (lane & 3), r = lane >> 2;
            *reinterpret_cast<float2*>(pw + NF_ + r * 528 + (nt * 8 + c) * 4) =
                make_float2(d0[0], d0[1]);
            *reinterpret_cast<float2*>(pw + NF_ + (r + 8) * 528 + (nt * 8 + c) * 4) =
                make_float2(d0[2], d0[3]);
            *reinterpret_cast<float2*>(pw + NF_ + r * 528 + ((nt + 1) * 8 + c) * 4) =
                make_float2(d1[0], d1[1]);
            *reinterpret_cast<float2*>(pw + NF_ + (r + 8) * 528 + ((nt + 1) * 8 + c) * 4) =
                make_float2(d1[2], d1[3]);
        }
        __syncwarp();

        // ---- agg over {i-1,i,i+1,i^8} + STG.128 ----
        float* ob = out + (size_t)b * 2048;
        #pragma unroll
        for (int i = 0; i < 16; i++) {
            int jn0 = (i > 0) ? i - 1 : i, jn2 = (i < 15) ? i + 1 : i;
            ull a0 = *reinterpret_cast<const ull*>(pw + ASH_ + ((i * 4 + myh) * 4 + 0) * 8);
            ull a1 = *reinterpret_cast<const ull*>(pw + ASH_ + ((i * 4 + myh) * 4 + 1) * 8);
            ull a2 = *reinterpret_cast<const ull*>(pw + ASH_ + ((i * 4 + myh) * 4 + 2) * 8);
            ull a3 = *reinterpret_cast<const ull*>(pw + ASH_ + ((i * 4 + myh) * 4 + 3) * 8);
            ull2x q0 = *reinterpret_cast<const ull2x*>(pw + NF_ + jn0 * 528 + lane * 16);
            ull2x q1 = *reinterpret_cast<const ull2x*>(pw + NF_ + i   * 528 + lane * 16);
            ull2x q2 = *reinterpret_cast<const ull2x*>(pw + NF_ + jn2 * 528 + lane * 16);
            ull2x q3 = *reinterpret_cast<const ull2x*>(pw + NF_ + (i ^ 8) * 528 + lane * 16);
            ull o0 = 0ull, o1 = 0ull;
            ffma2(o0, a0, q0.a); ffma2(o1, a0, q0.b);
            ffma2(o0, a1, q1.a); ffma2(o1, a1, q1.b);
            ffma2(o0, a2, q2.a); ffma2(o1, a2, q2.b);
            ffma2(o0, a3, q3.a); ffma2(o1, a3, q3.b);
            ull2x vv; vv.a = o0; vv.b = o1;
            *reinterpret_cast<ull2x*>(&ob[i * 128 + 4 * lane]) = vv;
        }
        __syncwarp();
    }
}

extern "C" void kernel_launch(void* const* d_in, const int* in_sizes, int n_in,
                              void* d_out, int out_size)
{
    const float* x  = (const float*)d_in[0];
    const float* W  = (const float*)d_in[1];
    const float* c2 = (const float*)d_in[2];
    const float* c3 = (const float*)d_in[3];
    float* out = (float*)d_out;
    int n_batch = in_sizes[0] / 1024;   // 32768

    select_av_kernel<<<1, 256>>>(c2, c3);
    cudaFuncSetAttribute(gat_kernel, cudaFuncAttributeMaxDynamicSharedMemorySize, SMEM_SZ);
    gat_kernel<<<296, 128, SMEM_SZ>>>(x, W, out, n_batch);
}

// round 15
// speedup vs baseline: 1.4182x; 1.1039x over previous
#include <cuda_runtime.h>
#include <cuda_bf16.h>
#include <cstdint>

// GAT B=32768, N=16, FIN=64, H=4, FO=32. nf = X@W via mma.sync m16n8k16
// bf16 3-split. R15: B fragments REGISTER-RESIDENT (loaded once), CTA
// processes 4 batches/group, warp owns one head (4 n-tiles). WT smem
// overlaid by runtime buffers after init -> 64.8KB -> 3 CTAs/SM.
typedef unsigned long long ull;
struct alignas(16) ull2x { ull a, b; };

// init-only region (overlaid by runtime buffers after fragment load)
#define WTHI 0
#define WTLO 18432
// runtime regions
#define A_B   0        // A(g) = g*4608: hi 2304 + lo 2304  (ends 18432)
#define NF_B  18432    // NF(g) = +g*8448 (16 rows x 528B)   (ends 52224)
#define SB_B  52224    // SB(g) = +g*512                      (ends 54272)
#define ASH_B 54272    // ASH(g)= +g*2048                     (ends 62464)
#define WFHI  62464    // wfold hi (outside overlay)
#define WFLO  63616
#define SMEM_SZ 64768  // 3 CTAs/SM (194 KB)

static __device__ __forceinline__ uint32_t s2u(const void* p) {
    uint32_t a;
    asm("{ .reg .u64 t; cvta.to.shared.u64 t, %1; cvt.u32.u64 %0, t; }" : "=r"(a) : "l"(p));
    return a;
}
static __device__ __forceinline__ void ffma2(ull& d, ull a, ull b) {
    asm("fma.rn.f32x2 %0, %1, %2, %0;" : "+l"(d) : "l"(a), "l"(b));
}
static __device__ __forceinline__ uint32_t cvt2(float lo, float hi) {
    uint32_t r; asm("cvt.rn.satfinite.bf16x2.f32 %0, %1, %2;" : "=r"(r) : "f"(hi), "f"(lo));
    return r;
}
static __device__ __forceinline__ void ldmx4(uint32_t& r0, uint32_t& r1, uint32_t& r2,
                                             uint32_t& r3, uint32_t addr) {
    asm volatile("ldmatrix.sync.aligned.m8n8.x4.shared.b16 {%0,%1,%2,%3}, [%4];"
                 : "=r"(r0), "=r"(r1), "=r"(r2), "=r"(r3) : "r"(addr));
}
static __device__ __forceinline__ void mma4(float* d, const uint32_t* a,
                                            uint32_t b0, uint32_t b1) {
    asm volatile("mma.sync.aligned.m16n8k16.row.col.f32.bf16.bf16.f32 "
                 "{%0,%1,%2,%3},{%4,%5,%6,%7},{%8,%9},{%0,%1,%2,%3};"
                 : "+f"(d[0]), "+f"(d[1]), "+f"(d[2]), "+f"(d[3])
                 : "r"(a[0]), "r"(a[1]), "r"(a[2]), "r"(a[3]), "r"(b0), "r"(b1));
}

__device__ float g_av[256];
__global__ void select_av_kernel(const float* __restrict__ ca, const float* __restrict__ cb) {
    __shared__ int nb; int t = threadIdx.x;
    if (t == 0) nb = 0;
    __syncthreads();
    float v = ca[t];
    if (!(v == 0.0f || v == 1.0f)) atomicAdd(&nb, 1);
    __syncthreads();
    g_av[t] = (nb > 0) ? ca[t] : cb[t];
}

__global__ void __launch_bounds__(128, 3)
gat_kernel(const float* __restrict__ x, const float* __restrict__ W,
           float* __restrict__ out, int n_groups)
{
    extern __shared__ char sm[];
    const uint32_t sb = s2u(sm);
    const int tid = threadIdx.x, lane = tid & 31, wid = tid >> 5;

    // ---- init: WT hi/lo (144B pitch) + wfold hi/lo ----
    for (int idx = tid; idx < 8192; idx += 128) {
        int cg = idx >> 6, f = idx & 63;
        float w = W[f * 128 + cg];
        __nv_bfloat16 h = __float2bfloat16_rn(w);
        *reinterpret_cast<__nv_bfloat16*>(sm + WTHI + cg * 144 + f * 2) = h;
        *reinterpret_cast<__nv_bfloat16*>(sm + WTLO + cg * 144 + f * 2) =
            __float2bfloat16_rn(w - __bfloat162float(h));
    }
    for (int e = tid; e < 512; e += 128) {
        int f = e >> 3, n = e & 7, side = n >> 2, h = n & 3;
        const float* wr = W + f * 128;
        const float* ar = g_av + h * 64 + side * 32;
        float s = 0.f;
        #pragma unroll 8
        for (int k = 0; k < 32; k++)
            s += (wr[k] + wr[32 + k] + wr[64 + k] + wr[96 + k]) * ar[k];
        __nv_bfloat16 hb = __float2bfloat16_rn(s);
        *reinterpret_cast<__nv_bfloat16*>(sm + WFHI + n * 144 + f * 2) = hb;
        *reinterpret_cast<__nv_bfloat16*>(sm + WFLO + n * 144 + f * 2) =
            __float2bfloat16_rn(s - __bfloat162float(hb));
    }
    __syncthreads();

    // ---- resident B fragments: warp w owns n-tiles 4w..4w+3 (head w) ----
    uint32_t bh[4][8], bl[4][8];
    #pragma unroll
    for (int tt = 0; tt < 4; tt++) {
        int nt = 4 * wid + tt;
        uint32_t wb = sb + WTHI + (nt * 8 + (lane & 7)) * 144 + (lane >> 3) * 16;
        ldmx4(bh[tt][0], bh[tt][1], bh[tt][2], bh[tt][3], wb);
        ldmx4(bh[tt][4], bh[tt][5], bh[tt][6], bh[tt][7], wb + 64);
        ldmx4(bl[tt][0], bl[tt][1], bl[tt][2], bl[tt][3], wb + (WTLO - WTHI));
        ldmx4(bl[tt][4], bl[tt][5], bl[tt][6], bl[tt][7], wb + (WTLO - WTHI) + 64);
    }
    __syncthreads();   // WT region may now be overlaid

    const int myh = lane >> 3;

    for (int grp = blockIdx.x; grp < n_groups; grp += gridDim.x) {
        const int b = grp * 4 + wid;   // this warp's batch
        // ---- X(b) -> bf16 hi/lo A tiles in A(wid) (144B pitch) ----
        char* pa = sm + A_B + wid * 4608;
        const float4* xg = reinterpret_cast<const float4*>(x + (size_t)b * 1024);
        #pragma unroll
        for (int t = 0; t < 8; t++) {
            int fid = t * 32 + lane;
            float4 v = xg[fid];
            uint32_t h01 = cvt2(v.x, v.y), h23 = cvt2(v.z, v.w);
            float l0 = v.x - __uint_as_float(h01 << 16);
            float l1 = v.y - __uint_as_float(h01 & 0xFFFF0000u);
            float l2 = v.z - __uint_as_float(h23 << 16);
            float l3 = v.w - __uint_as_float(h23 & 0xFFFF0000u);
            int off = (fid >> 4) * 144 + (fid & 15) * 8;
            *reinterpret_cast<uint2*>(pa + off) = make_uint2(h01, h23);
            *reinterpret_cast<uint2*>(pa + 2304 + off) = make_uint2(cvt2(l0, l1), cvt2(l2, l3));
        }
        __syncwarp();

        uint32_t ah[16], al[16];
        // ---- scores for own batch (A frags + wfold frags) ----
        {
            uint32_t ab = sb + A_B + wid * 4608 + (lane & 15) * 144 + (lane >> 4) * 16;
            #pragma unroll
            for (int kt = 0; kt < 4; kt++) {
                ldmx4(ah[4 * kt], ah[4 * kt + 1], ah[4 * kt + 2], ah[4 * kt + 3], ab + kt * 32);
                ldmx4(al[4 * kt], al[4 * kt + 1], al[4 * kt + 2], al[4 * kt + 3], ab + 2304 + kt * 32);
            }
            uint32_t fb = sb + WFHI + (lane & 7) * 144 + (lane >> 3) * 16;
            uint32_t fh[8], fl[8];
            ldmx4(fh[0], fh[1], fh[2], fh[3], fb);
            ldmx4(fh[4], fh[5], fh[6], fh[7], fb + 64);
            ldmx4(fl[0], fl[1], fl[2], fl[3], fb + (WFLO - WFHI));
            ldmx4(fl[4], fl[5], fl[6], fl[7], fb + (WFLO - WFHI) + 64);
            float sA[4] = {0, 0, 0, 0}, sB[4] = {0, 0, 0, 0}, sC[4] = {0, 0, 0, 0};
            #pragma unroll
            for (int kt = 0; kt < 4; kt++) {
                int bi = (kt >> 1) * 4 + (kt & 1) * 2;
                mma4(sA, &ah[4 * kt], fh[bi], fh[bi + 1]);
                mma4(sB, &al[4 * kt], fh[bi], fh[bi + 1]);
                mma4(sC, &ah[4 * kt], fl[bi], fl[bi + 1]);
            }
            char* psb = sm + SB_B + wid * 512;
            int c = 2 * (lane & 3), r = lane >> 2, side = c >> 2, cc = c & 3;
            *reinterpret_cast<float2*>(psb + (side * 16 + r) * 16 + cc * 4) =
                make_float2(sA[0] + sB[0] + sC[0], sA[1] + sB[1] + sC[1]);
            *reinterpret_cast<float2*>(psb + (side * 16 + r + 8) * 16 + cc * 4) =
                make_float2(sA[2] + sB[2] + sC[2], sA[3] + sB[3] + sC[3]);
        }
        __syncwarp();

        // ---- softmax for own batch -> ASH(wid) ----
        {
            char* psb = sm + SB_B + wid * 512;
            char* pash = sm + ASH_B + wid * 2048;
            int i = lane & 15, hp = lane >> 4;
            float2 s1v = *reinterpret_cast<const float2*>(psb + i * 16 + hp * 8);
            int jn[4] = { (i > 0) ? i - 1 : i, i, (i < 15) ? i + 1 : i, i ^ 8 };
            bool vl[4] = { i > 0, true, i < 15, true };
            float t0[4], t1[4];
            float m0 = -1e30f, m1 = -1e30f;
            #pragma unroll
            for (int s = 0; s < 4; s++) {
                float2 s2v = *reinterpret_cast<const float2*>(psb + 256 + jn[s] * 16 + hp * 8);
                float a0 = s1v.x + s2v.x; a0 = fmaxf(a0, 0.2f * a0);
                float a1 = s1v.y + s2v.y; a1 = fmaxf(a1, 0.2f * a1);
                t0[s] = vl[s] ? a0 : -1e30f;
                t1[s] = vl[s] ? a1 : -1e30f;
                m0 = fmaxf(m0, t0[s]); m1 = fmaxf(m1, t1[s]);
            }
            float sum0 = 0.f, sum1 = 0.f;
            #pragma unroll
            for (int s = 0; s < 4; s++) {
                t0[s] = __expf(t0[s] - m0);
                t1[s] = __expf(t1[s] - m1);
                sum0 += t0[s]; sum1 += t1[s];
            }
            float r0 = __fdividef(1.f, sum0), r1 = __fdividef(1.f, sum1);
            #pragma unroll
            for (int s = 0; s < 4; s++) {
                float v0 = t0[s] * r0, v1 = t1[s] * r1;
                *reinterpret_cast<float2*>(pash + ((i * 4 + 2 * hp) * 4 + s) * 8) =
                    make_float2(v0, v0);
                *reinterpret_cast<float2*>(pash + ((i * 4 + 2 * hp + 1) * 4 + s) * 8) =
                    make_float2(v1, v1);
            }
        }
        __syncthreads();   // all A tiles ready

        // ---- GEMM: all 4 batches vs resident B (staggered start) ----
        #pragma unroll
        for (int k = 0; k < 4; k++) {
            int g = (wid + k) & 3;
            uint32_t ab = sb + A_B + g * 4608 + (lane & 15) * 144 + (lane >> 4) * 16;
            #pragma unroll
            for (int kt = 0; kt < 4; kt++) {
                ldmx4(ah[4 * kt], ah[4 * kt + 1], ah[4 * kt + 2], ah[4 * kt + 3], ab + kt * 32);
                ldmx4(al[4 * kt], al[4 * kt + 1], al[4 * kt + 2], al[4 * kt + 3], ab + 2304 + kt * 32);
            }
            char* pnf = sm + NF_B + g * 8448;
            #pragma unroll
            for (int tt = 0; tt < 4; tt++) {
                float dA[4] = {0, 0, 0, 0}, dB[4] = {0, 0, 0, 0}, dC[4] = {0, 0, 0, 0};
                #pragma unroll
                for (int kt = 0; kt < 4; kt++) {
                    int bi = (kt >> 1) * 4 + (kt & 1) * 2;
                    mma4(dA, &ah[4 * kt], bh[tt][bi], bh[tt][bi + 1]);
                    mma4(dB, &al[4 * kt], bh[tt][bi], bh[tt][bi + 1]);
                    mma4(dC, &ah[4 * kt], bl[tt][bi], bl[tt][bi + 1]);
                }
                int c = 2 * (lane & 3), r = lane >> 2;
                int colb = (4 * wid + tt) * 8 + c;
                *reinterpret_cast<float2*>(pnf + r * 528 + colb * 4) =
                    make_float2(dA[0] + dB[0] + dC[0], dA[1] + dB[1] + dC[1]);
                *reinterpret_cast<float2*>(pnf + (r + 8) * 528 + colb * 4) =
                    make_float2(dA[2] + dB[2] + dC[2], dA[3] + dB[3] + dC[3]);
            }
        }
        __syncthreads();   // NF complete

        // ---- agg own batch over {i-1,i,i+1,i^8} + STG.128 ----
        {
            char* pnf = sm + NF_B + wid * 8448;
            char* pash = sm + ASH_B + wid * 2048;
            float* ob = out + (size_t)b * 2048;
            #pragma unroll
            for (int i = 0; i < 16; i++) {
                int jn0 = (i > 0) ? i - 1 : i, jn2 = (i < 15) ? i + 1 : i;
                ull a0 = *reinterpret_cast<const ull*>(pash + ((i * 4 + myh) * 4 + 0) * 8);
                ull a1 = *reinterpret_cast<const ull*>(pash + ((i * 4 + myh) * 4 + 1) * 8);
                ull a2 = *reinterpret_cast<const ull*>(pash + ((i * 4 + myh) * 4 + 2) * 8);
                ull a3 = *reinterpret_cast<const ull*>(pash + ((i * 4 + myh) * 4 + 3) * 8);
                ull2x q0 = *reinterpret_cast<const ull2x*>(pnf + jn0 * 528 + lane * 16);
                ull2x q1 = *reinterpret_cast<const ull2x*>(pnf + i   * 528 + lane * 16);
                ull2x q2 = *reinterpret_cast<const ull2x*>(pnf + jn2 * 528 + lane * 16);
                ull2x q3 = *reinterpret_cast<const ull2x*>(pnf + (i ^ 8) * 528 + lane * 16);
                ull o0 = 0ull, o1 = 0ull;
                ffma2(o0, a0, q0.a); ffma2(o1, a0, q0.b);
                ffma2(o0, a1, q1.a); ffma2(o1, a1, q1.b);
                ffma2(o0, a2, q2.a); ffma2(o1, a2, q2.b);
                ffma2(o0, a3, q3.a); ffma2(o1, a3, q3.b);
                ull2x vv; vv.a = o0; vv.b = o1;
                *reinterpret_cast<ull2x*>(&ob[i * 128 + 4 * lane]) = vv;
            }
        }
        __syncthreads();   // buffers reusable next group
    }
}

extern "C" void kernel_launch(void* const* d_in, const int* in_sizes, int n_in,
                              void* d_out, int out_size)
{
    const float* x  = (const float*)d_in[0];
    const float* W  = (const float*)d_in[1];
    const float* c2 = (const float*)d_in[2];
    const float* c3 = (const float*)d_in[3];
    float* out = (float*)d_out;
    int n_batch = in_sizes[0] / 1024;   // 32768
    int n_groups = n_batch / 4;         // 8192

    select_av_kernel<<<1, 256>>>(c2, c3);
    cudaFuncSetAttribute(gat_kernel, cudaFuncAttributeMaxDynamicSharedMemorySize, SMEM_SZ);
    gat_kernel<<<444, 128, SMEM_SZ>>>(x, W, out, n_groups);
}

// round 16
// speedup vs baseline: 1.5739x; 1.1098x over previous
#include <cuda_runtime.h>
#include <cuda_bf16.h>
#include <cstdint>

// GAT B=32768, N=16, FIN=64, H=4, FO=32. nf = X@W via mma.sync m16n8k16
// bf16 3-split, resident-B (R15). R16: rolling-window agg (NF rows read
// once for the sliding {i-1,i,i+1} + once for i^8), ASH packed float4.
typedef unsigned long long ull;
struct alignas(16) ull2x { ull a, b; };

// init-only region (overlaid by runtime buffers after fragment load)
#define WTHI 0
#define WTLO 18432
// runtime regions
#define A_B   0        // A(g) = g*4608: hi 2304 + lo 2304  (ends 18432)
#define NF_B  18432    // NF(g) = +g*8448 (16 rows x 528B)   (ends 52224)
#define SB_B  52224    // SB(g) = +g*512                      (ends 54272)
#define ASH_B 54272    // ASH(g)= +g*1024 (16 i x 4 h x 16B)  (ends 58368)
#define WFHI  58368    // wfold hi (outside overlay)
#define WFLO  59520
#define SMEM_SZ 60672  // 3 CTAs/SM

static __device__ __forceinline__ uint32_t s2u(const void* p) {
    uint32_t a;
    asm("{ .reg .u64 t; cvta.to.shared.u64 t, %1; cvt.u32.u64 %0, t; }" : "=r"(a) : "l"(p));
    return a;
}
static __device__ __forceinline__ void ffma2(ull& d, ull a, ull b) {
    asm("fma.rn.f32x2 %0, %1, %2, %0;" : "+l"(d) : "l"(a), "l"(b));
}
static __device__ __forceinline__ ull pack2(float lo, float hi) {
    ull r; asm("mov.b64 %0, {%1, %2};" : "=l"(r) : "f"(lo), "f"(hi)); return r;
}
static __device__ __forceinline__ uint32_t cvt2(float lo, float hi) {
    uint32_t r; asm("cvt.rn.satfinite.bf16x2.f32 %0, %1, %2;" : "=r"(r) : "f"(hi), "f"(lo));
    return r;
}
static __device__ __forceinline__ void ldmx4(uint32_t& r0, uint32_t& r1, uint32_t& r2,
                                             uint32_t& r3, uint32_t addr) {
    asm volatile("ldmatrix.sync.aligned.m8n8.x4.shared.b16 {%0,%1,%2,%3}, [%4];"
                 : "=r"(r0), "=r"(r1), "=r"(r2), "=r"(r3) : "r"(addr));
}
static __device__ __forceinline__ void mma4(float* d, const uint32_t* a,
                                            uint32_t b0, uint32_t b1) {
    asm volatile("mma.sync.aligned.m16n8k16.row.col.f32.bf16.bf16.f32 "
                 "{%0,%1,%2,%3},{%4,%5,%6,%7},{%8,%9},{%0,%1,%2,%3};"
                 : "+f"(d[0]), "+f"(d[1]), "+f"(d[2]), "+f"(d[3])
                 : "r"(a[0]), "r"(a[1]), "r"(a[2]), "r"(a[3]), "r"(b0), "r"(b1));
}

__device__ float g_av[256];
__global__ void select_av_kernel(const float* __restrict__ ca, const float* __restrict__ cb) {
    __shared__ int nb; int t = threadIdx.x;
    if (t == 0) nb = 0;
    __syncthreads();
    float v = ca[t];
    if (!(v == 0.0f || v == 1.0f)) atomicAdd(&nb, 1);
    __syncthreads();
    g_av[t] = (nb > 0) ? ca[t] : cb[t];
}

__global__ void __launch_bounds__(128, 3)
gat_kernel(const float* __restrict__ x, const float* __restrict__ W,
           float* __restrict__ out, int n_groups)
{
    extern __shared__ char sm[];
    const uint32_t sb = s2u(sm);
    const int tid = threadIdx.x, lane = tid & 31, wid = tid >> 5;

    // ---- init: WT hi/lo (144B pitch) + wfold hi/lo ----
    for (int idx = tid; idx < 8192; idx += 128) {
        int cg = idx >> 6, f = idx & 63;
        float w = W[f * 128 + cg];
        __nv_bfloat16 h = __float2bfloat16_rn(w);
        *reinterpret_cast<__nv_bfloat16*>(sm + WTHI + cg * 144 + f * 2) = h;
        *reinterpret_cast<__nv_bfloat16*>(sm + WTLO + cg * 144 + f * 2) =
            __float2bfloat16_rn(w - __bfloat162float(h));
    }
    for (int e = tid; e < 512; e += 128) {
        int f = e >> 3, n = e & 7, side = n >> 2, h = n & 3;
        const float* wr = W + f * 128;
        const float* ar = g_av + h * 64 + side * 32;
        float s = 0.f;
        #pragma unroll 8
        for (int k = 0; k < 32; k++)
            s += (wr[k] + wr[32 + k] + wr[64 + k] + wr[96 + k]) * ar[k];
        __nv_bfloat16 hb = __float2bfloat16_rn(s);
        *reinterpret_cast<__nv_bfloat16*>(sm + WFHI + n * 144 + f * 2) = hb;
        *reinterpret_cast<__nv_bfloat16*>(sm + WFLO + n * 144 + f * 2) =
            __float2bfloat16_rn(s - __bfloat162float(hb));
    }
    __syncthreads();

    // ---- resident B fragments: warp w owns n-tiles 4w..4w+3 (head w) ----
    uint32_t bh[4][8], bl[4][8];
    #pragma unroll
    for (int tt = 0; tt < 4; tt++) {
        int nt = 4 * wid + tt;
        uint32_t wb = sb + WTHI + (nt * 8 + (lane & 7)) * 144 + (lane >> 3) * 16;
        ldmx4(bh[tt][0], bh[tt][1], bh[tt][2], bh[tt][3], wb);
        ldmx4(bh[tt][4], bh[tt][5], bh[tt][6], bh[tt][7], wb + 64);
        ldmx4(bl[tt][0], bl[tt][1], bl[tt][2], bl[tt][3], wb + (WTLO - WTHI));
        ldmx4(bl[tt][4], bl[tt][5], bl[tt][6], bl[tt][7], wb + (WTLO - WTHI) + 64);
    }
    __syncthreads();   // WT region may now be overlaid

    const int myh = lane >> 3;

    for (int grp = blockIdx.x; grp < n_groups; grp += gridDim.x) {
        const int b = grp * 4 + wid;   // this warp's batch
        // ---- X(b) -> bf16 hi/lo A tiles in A(wid) (144B pitch) ----
        char* pa = sm + A_B + wid * 4608;
        const float4* xg = reinterpret_cast<const float4*>(x + (size_t)b * 1024);
        #pragma unroll
        for (int t = 0; t < 8; t++) {
            int fid = t * 32 + lane;
            float4 v = xg[fid];
            uint32_t h01 = cvt2(v.x, v.y), h23 = cvt2(v.z, v.w);
            float l0 = v.x - __uint_as_float(h01 << 16);
            float l1 = v.y - __uint_as_float(h01 & 0xFFFF0000u);
            float l2 = v.z - __uint_as_float(h23 << 16);
            float l3 = v.w - __uint_as_float(h23 & 0xFFFF0000u);
            int off = (fid >> 4) * 144 + (fid & 15) * 8;
            *reinterpret_cast<uint2*>(pa + off) = make_uint2(h01, h23);
            *reinterpret_cast<uint2*>(pa + 2304 + off) = make_uint2(cvt2(l0, l1), cvt2(l2, l3));
        }
        __syncwarp();

        uint32_t ah[16], al[16];
        // ---- scores for own batch (A frags + wfold frags) ----
        {
            uint32_t ab = sb + A_B + wid * 4608 + (lane & 15) * 144 + (lane >> 4) * 16;
            #pragma unroll
            for (int kt = 0; kt < 4; kt++) {
                ldmx4(ah[4 * kt], ah[4 * kt + 1], ah[4 * kt + 2], ah[4 * kt + 3], ab + kt * 32);
                ldmx4(al[4 * kt], al[4 * kt + 1], al[4 * kt + 2], al[4 * kt + 3], ab + 2304 + kt * 32);
            }
            uint32_t fb = sb + WFHI + (lane & 7) * 144 + (lane >> 3) * 16;
            uint32_t fh[8], fl[8];
            ldmx4(fh[0], fh[1], fh[2], fh[3], fb);
            ldmx4(fh[4], fh[5], fh[6], fh[7], fb + 64);
            ldmx4(fl[0], fl[1], fl[2], fl[3], fb + (WFLO - WFHI));
            ldmx4(fl[4], fl[5], fl[6], fl[7], fb + (WFLO - WFHI) + 64);
            float s[4] = {0, 0, 0, 0};
            #pragma unroll
            for (int kt = 0; kt < 4; kt++) {
                int bi = (kt >> 1) * 4 + (kt & 1) * 2;
                mma4(s, &ah[4 * kt], fh[bi], fh[bi + 1]);
                mma4(s, &al[4 * kt], fh[bi], fh[bi + 1]);
                mma4(s, &ah[4 * kt], fl[bi], fl[bi + 1]);
            }
            char* psb = sm + SB_B + wid * 512;
            int c = 2 * (lane & 3), r = lane >> 2, side = c >> 2, cc = c & 3;
            *reinterpret_cast<float2*>(psb + (side * 16 + r) * 16 + cc * 4) =
                make_float2(s[0], s[1]);
            *reinterpret_cast<float2*>(psb + (side * 16 + r + 8) * 16 + cc * 4) =
                make_float2(s[2], s[3]);
        }
        __syncwarp();

        // ---- softmax for own batch -> ASH(wid), packed float4 per (i,h) ----
        {
            char* psb = sm + SB_B + wid * 512;
            char* pash = sm + ASH_B + wid * 1024;
            int i = lane & 15, hp = lane >> 4;
            float2 s1v = *reinterpret_cast<const float2*>(psb + i * 16 + hp * 8);
            int jn[4] = { (i > 0) ? i - 1 : i, i, (i < 15) ? i + 1 : i, i ^ 8 };
            bool vl[4] = { i > 0, true, i < 15, true };
            float t0[4], t1[4];
            float m0 = -1e30f, m1 = -1e30f;
            #pragma unroll
            for (int s = 0; s < 4; s++) {
                float2 s2v = *reinterpret_cast<const float2*>(psb + 256 + jn[s] * 16 + hp * 8);
                float a0 = s1v.x + s2v.x; a0 = fmaxf(a0, 0.2f * a0);
                float a1 = s1v.y + s2v.y; a1 = fmaxf(a1, 0.2f * a1);
                t0[s] = vl[s] ? a0 : -1e30f;
                t1[s] = vl[s] ? a1 : -1e30f;
                m0 = fmaxf(m0, t0[s]); m1 = fmaxf(m1, t1[s]);
            }
            float sum0 = 0.f, sum1 = 0.f;
            #pragma unroll
            for (int s = 0; s < 4; s++) {
                t0[s] = __expf(t0[s] - m0);
                t1[s] = __expf(t1[s] - m1);
                sum0 += t0[s]; sum1 += t1[s];
            }
            float r0 = __fdividef(1.f, sum0), r1 = __fdividef(1.f, sum1);
            *reinterpret_cast<float4*>(pash + (i * 4 + 2 * hp) * 16) =
                make_float4(t0[0] * r0, t0[1] * r0, t0[2] * r0, t0[3] * r0);
            *reinterpret_cast<float4*>(pash + (i * 4 + 2 * hp + 1) * 16) =
                make_float4(t1[0] * r1, t1[1] * r1, t1[2] * r1, t1[3] * r1);
        }
        __syncthreads();   // all A tiles ready

        // ---- GEMM: all 4 batches vs resident B (staggered start) ----
        #pragma unroll
        for (int k = 0; k < 4; k++) {
            int g = (wid + k) & 3;
            uint32_t ab = sb + A_B + g * 4608 + (lane & 15) * 144 + (lane >> 4) * 16;
            #pragma unroll
            for (int kt = 0; kt < 4; kt++) {
                ldmx4(ah[4 * kt], ah[4 * kt + 1], ah[4 * kt + 2], ah[4 * kt + 3], ab + kt * 32);
                ldmx4(al[4 * kt], al[4 * kt + 1], al[4 * kt + 2], al[4 * kt + 3], ab + 2304 + kt * 32);
            }
            char* pnf = sm + NF_B + g * 8448;
            #pragma unroll
            for (int tt = 0; tt < 4; tt++) {
                float d[4] = {0, 0, 0, 0};
                #pragma unroll
                for (int kt = 0; kt < 4; kt++) {
                    int bi = (kt >> 1) * 4 + (kt & 1) * 2;
                    mma4(d, &ah[4 * kt], bh[tt][bi], bh[tt][bi + 1]);
                    mma4(d, &al[4 * kt], bh[tt][bi], bh[tt][bi + 1]);
                    mma4(d, &ah[4 * kt], bl[tt][bi], bl[tt][bi + 1]);
                }
                int c = 2 * (lane & 3), r = lane >> 2;
                int colb = (4 * wid + tt) * 8 + c;
                *reinterpret_cast<float2*>(pnf + r * 528 + colb * 4) = make_float2(d[0], d[1]);
                *reinterpret_cast<float2*>(pnf + (r + 8) * 528 + colb * 4) = make_float2(d[2], d[3]);
            }
        }
        __syncthreads();   // NF complete

        // ---- agg own batch: rolling window {i-1,i,i+1} + cross i^8 ----
        {
            char* pnf = sm + NF_B + wid * 8448;
            char* pash = sm + ASH_B + wid * 1024;
            float* ob = out + (size_t)b * 2048;
            const uint32_t lo = lane * 16;
            ull2x qa, qb, qc;
            qb = *reinterpret_cast<const ull2x*>(pnf + 0 * 528 + lo);   // row 0
            qc = *reinterpret_cast<const ull2x*>(pnf + 1 * 528 + lo);   // row 1
            qa = qb;   // finite dummy; attn slot0=0 at i=0
            #pragma unroll
            for (int i = 0; i < 16; i++) {
                ull2x qx = *reinterpret_cast<const ull2x*>(pnf + (i ^ 8) * 528 + lo);
                float4 av = *reinterpret_cast<const float4*>(pash + (i * 4 + myh) * 16);
                ull a0 = pack2(av.x, av.x), a1 = pack2(av.y, av.y);
                ull a2 = pack2(av.z, av.z), a3 = pack2(av.w, av.w);
                ull o0 = 0ull, o1 = 0ull;
                ffma2(o0, a0, qa.a); ffma2(o1, a0, qa.b);
                ffma2(o0, a1, qb.a); ffma2(o1, a1, qb.b);
                ffma2(o0, a2, qc.a); ffma2(o1, a2, qc.b);
                ffma2(o0, a3, qx.a); ffma2(o1, a3, qx.b);
                ull2x vv; vv.a = o0; vv.b = o1;
                *reinterpret_cast<ull2x*>(&ob[i * 128 + 4 * lane]) = vv;
                qa = qb; qb = qc;
                if (i < 14)
                    qc = *reinterpret_cast<const ull2x*>(pnf + (i + 2) * 528 + lo);
            }
        }
        __syncthreads();   // buffers reusable next group
    }
}

extern "C" void kernel_launch(void* const* d_in, const int* in_sizes, int n_in,
                              void* d_out, int out_size)
{
    const float* x  = (const float*)d_in[0];
    const float* W  = (const float*)d_in[1];
    const float* c2 = (const float*)d_in[2];
    const float* c3 = (const float*)d_in[3];
    float* out = (float*)d_out;
    int n_batch = in_sizes[0] / 1024;   // 32768
    int n_groups = n_batch / 4;         // 8192

    select_av_kernel<<<1, 256>>>(c2, c3);
    cudaFuncSetAttribute(gat_kernel, cudaFuncAttributeMaxDynamicSharedMemorySize, SMEM_SZ);
    gat_kernel<<<444, 128, SMEM_SZ>>>(x, W, out, n_groups);
}